// round 12
// baseline (speedup 1.0000x reference)
#include <cuda_runtime.h>
#include <cuda_bf16.h>
#include <cstdint>

// Problem constants (shapes fixed by dataset)
#define BB   16      // batch
#define CC   32      // channels in added; original has CC+1
#define HH   256     // grid H = W
#define TT   20      // boxes per batch
#define CELLS (HH*HH)
#define SEGS  (CELLS/32)     // 32-cell row segments per batch = 2048
#define VOX  0.8f
#define INVVOX 1.25f

#define C_BLOCKS 512         // consumer blocks (4096 warps -> ~1 entry each)
#define C_THREADS 256
#define NWARPS  (C_BLOCKS * (C_THREADS/32))

// Order-pinned scalar load: forces ptxas to keep the whole batch in flight.
#define LDGU32(dst, p)                                        \
    asm volatile("ld.global.nc.u32 %0, [%1];"                 \
                 : "=r"(dst) : "l"(p))

// Persistent scratch (no cudaMalloc). Static zero-init; consumers reset what
// they read so graph replays start clean.
__device__ unsigned int g_segmask[BB * SEGS];    // bit per cell in segment
__device__ unsigned int g_wlist[BB * SEGS];      // packed (b<<11)|seg
__device__ unsigned int g_wcount;
__device__ unsigned int g_inter[BB];
__device__ unsigned int g_union[BB];
__device__ unsigned int g_ticket;

// ---------------------------------------------------------------------------
// K1: rasterize boxes; claim 32-cell segments via atomicOr; first claimer
// appends the segment to the worklist (warp-aggregated).
// ---------------------------------------------------------------------------
__global__ void __launch_bounds__(128)
k_rasterize(const float* __restrict__ boxes) {
    const int bt = blockIdx.x;            // 0 .. B*T-1
    const int b  = bt / TT;
    const float* bx = boxes + (size_t)bt * 7;

    const float cx = bx[0], cy = bx[1], cz = bx[2];
    const float dx = bx[3], dy = bx[4], dz = bx[5], yaw = bx[6];

    // z test constant per box: |0.8 - cz| <= dz/2 (reference uses <=)
    if (fabsf(VOX - cz) > 0.5f * dz) return;

    const float c  = cosf(yaw), s = sinf(yaw);
    const float hx = 0.5f * dx, hy = 0.5f * dy;

    // rotated-box AABB (meters), +1 cell safety margin
    const float ax = hx * fabsf(c) + hy * fabsf(s);
    const float ay = hx * fabsf(s) + hy * fabsf(c);
    const int i0 = max(0,      (int)floorf((cx - ax) * INVVOX) - 1);
    const int i1 = min(HH - 1, (int)ceilf ((cx + ax) * INVVOX) + 1);
    const int j0 = max(0,      (int)floorf((cy - ay) * INVVOX) - 1);
    const int j1 = min(HH - 1, (int)ceilf ((cy + ay) * INVVOX) + 1);
    const int ni = i1 - i0 + 1, nj = j1 - j0 + 1;
    const int n  = ni * nj;

    const int lane = threadIdx.x & 31;
    unsigned int* segmask = g_segmask + (size_t)b * SEGS;

    // warp-uniform trip count so ballots are safe
    for (int k = threadIdx.x; (k - lane) < n; k += blockDim.x) {
        bool append = false;
        unsigned int ent = 0u;
        if (k < n) {
            const int i = i0 + k / nj;
            const int j = j0 + k % nj;
            const float px = (float)i * VOX - cx;
            const float py = (float)j * VOX - cy;
            const float rx = fmaf(py, s,  px * c);      //  px*c + py*s
            const float ry = fmaf(py, c, -px * s);      // -px*s + py*c
            if (fabsf(rx) < hx && fabsf(ry) < hy) {
                const int cell = i * HH + j;
                const int seg  = cell >> 5;
                const unsigned int bit = 1u << (cell & 31);
                const unsigned int old = atomicOr(&segmask[seg], bit);
                if (old == 0u) {                        // first claim
                    append = true;
                    ent = ((unsigned)b << 11) | (unsigned)seg;
                }
            }
        }
        const unsigned int bal = __ballot_sync(0xFFFFFFFFu, append);
        if (bal) {
            unsigned int base = 0u;
            if (lane == 0) base = atomicAdd(&g_wcount, (unsigned)__popc(bal));
            base = __shfl_sync(0xFFFFFFFFu, base, 0);
            if (append)
                g_wlist[base + __popc(bal & ((1u << lane) - 1u))] = ent;
        }
    }
}

// ---------------------------------------------------------------------------
// K2: consume worklist. One 32-cell segment per warp iteration; lane = cell.
// Channel loop as 4 order-pinned batches of 16 loads -> flight 16 guaranteed.
// Self-cleans all scratch; last block finalizes the scalar.
// ---------------------------------------------------------------------------
__global__ void __launch_bounds__(C_THREADS)
k_consume(const float* __restrict__ added,
          const float* __restrict__ orig,
          float* __restrict__ out) {
    const int lane = threadIdx.x & 31;
    const int wid  = threadIdx.x >> 5;
    const int gw   = blockIdx.x * (C_THREADS / 32) + wid;   // global warp id

    __shared__ unsigned int s_i[BB], s_u[BB];
    if (threadIdx.x < BB) { s_i[threadIdx.x] = 0u; s_u[threadIdx.x] = 0u; }
    __syncthreads();

    const unsigned int nw = g_wcount;
    const unsigned int* au = (const unsigned int*)added;
    const unsigned int* ou = (const unsigned int*)orig;

    for (unsigned int e = gw; e < nw; e += NWARPS) {
        const unsigned int ent = g_wlist[e];
        const int seg = ent & (SEGS - 1);
        const int b   = ent >> 11;
        const int idx = seg * 32 + lane;              // cell index in plane

        const unsigned int* ap = au + ((size_t)b * CC)         * CELLS + idx;
        const unsigned int* op = ou + ((size_t)b * (CC+1) + 1) * CELLS + idx;

        unsigned int pa = 0u, po = 0u;                // per-cell OR over channels
        {
            unsigned int v[16];
            #pragma unroll
            for (int u = 0; u < 16; u++) LDGU32(v[u], ap + (size_t)u * CELLS);
            #pragma unroll
            for (int u = 0; u < 16; u++) pa |= v[u];
            #pragma unroll
            for (int u = 0; u < 16; u++) LDGU32(v[u], ap + (size_t)(16 + u) * CELLS);
            #pragma unroll
            for (int u = 0; u < 16; u++) pa |= v[u];
            #pragma unroll
            for (int u = 0; u < 16; u++) LDGU32(v[u], op + (size_t)u * CELLS);
            #pragma unroll
            for (int u = 0; u < 16; u++) po |= v[u];
            #pragma unroll
            for (int u = 0; u < 16; u++) LDGU32(v[u], op + (size_t)(16 + u) * CELLS);
            #pragma unroll
            for (int u = 0; u < 16; u++) po |= v[u];
        }

        const unsigned int mw = g_segmask[b * SEGS + seg];
        if (lane == 0) g_segmask[b * SEGS + seg] = 0u;   // self-clean

        const bool m = (mw >> lane) & 1u;
        const bool p = m && (pa != 0u);               // sum!=0 <=> any bit (nonneg)
        const bool o = m && (po != 0u);
        const unsigned int bi = __ballot_sync(0xFFFFFFFFu, p && o);
        const unsigned int bu = __ballot_sync(0xFFFFFFFFu, p || o);
        if (lane == 0) {
            if (bi) atomicAdd(&s_i[b], (unsigned)__popc(bi));
            if (bu) atomicAdd(&s_u[b], (unsigned)__popc(bu));
        }
    }
    __syncthreads();

    // flush block accumulators to global
    if (threadIdx.x < BB) {
        const unsigned int vi = s_i[threadIdx.x];
        const unsigned int vu = s_u[threadIdx.x];
        if (vi) atomicAdd(&g_inter[threadIdx.x], vi);
        if (vu) atomicAdd(&g_union[threadIdx.x], vu);
    }

    // ---- last-block finalization (+ scratch reset for next replay) --------
    __shared__ unsigned int s_last;
    if (threadIdx.x == 0) {
        __threadfence();
        s_last = (atomicAdd(&g_ticket, 1u) == (unsigned)(C_BLOCKS - 1)) ? 1u : 0u;
    }
    __syncthreads();
    if (s_last && wid == 0) {
        float iou = 0.0f;
        if (lane < BB) {
            const unsigned int ai  = g_inter[lane];
            const unsigned int au2 = g_union[lane];
            g_inter[lane] = 0u;                      // reset for next replay
            g_union[lane] = 0u;
            iou = (float)ai / fmaxf((float)au2, 1.0f);
        }
        #pragma unroll
        for (int off = 16; off > 0; off >>= 1)
            iou += __shfl_xor_sync(0xFFFFFFFFu, iou, off);
        if (lane == 0) {
            out[0] = (float)TT * iou / (float)BB;
            g_wcount = 0u;                           // reset worklist count
            __threadfence();
            g_ticket = 0u;                           // reset ticket
        }
    }
}

// ---------------------------------------------------------------------------
extern "C" void kernel_launch(void* const* d_in, const int* in_sizes, int n_in,
                              void* d_out, int out_size) {
    const float* added = (const float*)d_in[0];   // (16,32,256,256)
    const float* orig  = (const float*)d_in[1];   // (16,33,256,256)
    const float* boxes = (const float*)d_in[2];   // (16,20,7)
    (void)in_sizes; (void)n_in; (void)out_size;   // tf_ego unused

    k_rasterize<<<BB * TT, 128>>>(boxes);
    k_consume<<<C_BLOCKS, C_THREADS>>>(added, orig, (float*)d_out);
}

// round 13
// speedup vs baseline: 1.1842x; 1.1842x over previous
#include <cuda_runtime.h>
#include <cuda_bf16.h>
#include <cstdint>

// Problem constants (shapes fixed by dataset)
#define BB   16      // batch
#define CC   32      // channels in added; original has CC+1
#define HH   256     // grid H = W
#define TT   20      // boxes per batch
#define CELLS (HH*HH)
#define SEGS  (CELLS/32)     // 32-cell row segments per batch = 2048
#define VOX  0.8f
#define INVVOX 1.25f

#define C_BLOCKS 512
#define C_THREADS 256
#define NWARPS  (C_BLOCKS * (C_THREADS/32))

// One asm statement = opaque block: all 16 outputs (4 x v4 loads spanning 16
// channel planes) are forced live simultaneously -> true flight >= 4 lines/lane.
// Channel-plane stride = CELLS*4 = 262144 B; each load steps 4 planes = 1 MiB.
#define LDGB16(v, p)                                                          \
    asm volatile(                                                             \
        "ld.global.nc.v4.u32 {%0,%1,%2,%3},    [%16];\n\t"                    \
        "ld.global.nc.v4.u32 {%4,%5,%6,%7},    [%16+1048576];\n\t"            \
        "ld.global.nc.v4.u32 {%8,%9,%10,%11},  [%16+2097152];\n\t"            \
        "ld.global.nc.v4.u32 {%12,%13,%14,%15},[%16+3145728];\n\t"            \
        : "=r"((v)[0].x), "=r"((v)[0].y), "=r"((v)[0].z), "=r"((v)[0].w),     \
          "=r"((v)[1].x), "=r"((v)[1].y), "=r"((v)[1].z), "=r"((v)[1].w),     \
          "=r"((v)[2].x), "=r"((v)[2].y), "=r"((v)[2].z), "=r"((v)[2].w),     \
          "=r"((v)[3].x), "=r"((v)[3].y), "=r"((v)[3].z), "=r"((v)[3].w)      \
        : "l"(p))

// Persistent scratch (no cudaMalloc). Static zero-init; consumers reset what
// they read so graph replays start clean.
__device__ unsigned int g_segmask[BB * SEGS];    // bit per cell in segment
__device__ unsigned int g_wlist[BB * SEGS];      // packed (b<<11)|seg
__device__ unsigned int g_wcount;
__device__ unsigned int g_inter[BB];
__device__ unsigned int g_union[BB];
__device__ unsigned int g_ticket;

// ---------------------------------------------------------------------------
// K1: rasterize boxes; claim 32-cell segments via atomicOr; first claimer
// appends the segment to the worklist (warp-aggregated).
// ---------------------------------------------------------------------------
__global__ void __launch_bounds__(128)
k_rasterize(const float* __restrict__ boxes) {
    const int bt = blockIdx.x;            // 0 .. B*T-1
    const int b  = bt / TT;
    const float* bx = boxes + (size_t)bt * 7;

    const float cx = bx[0], cy = bx[1], cz = bx[2];
    const float dx = bx[3], dy = bx[4], dz = bx[5], yaw = bx[6];

    // z test constant per box: |0.8 - cz| <= dz/2 (reference uses <=)
    if (fabsf(VOX - cz) > 0.5f * dz) return;

    const float c  = cosf(yaw), s = sinf(yaw);
    const float hx = 0.5f * dx, hy = 0.5f * dy;

    // rotated-box AABB (meters), +1 cell safety margin
    const float ax = hx * fabsf(c) + hy * fabsf(s);
    const float ay = hx * fabsf(s) + hy * fabsf(c);
    const int i0 = max(0,      (int)floorf((cx - ax) * INVVOX) - 1);
    const int i1 = min(HH - 1, (int)ceilf ((cx + ax) * INVVOX) + 1);
    const int j0 = max(0,      (int)floorf((cy - ay) * INVVOX) - 1);
    const int j1 = min(HH - 1, (int)ceilf ((cy + ay) * INVVOX) + 1);
    const int ni = i1 - i0 + 1, nj = j1 - j0 + 1;
    const int n  = ni * nj;

    const int lane = threadIdx.x & 31;
    unsigned int* segmask = g_segmask + (size_t)b * SEGS;

    // warp-uniform trip count so ballots are safe
    for (int k = threadIdx.x; (k - lane) < n; k += blockDim.x) {
        bool append = false;
        unsigned int ent = 0u;
        if (k < n) {
            const int i = i0 + k / nj;
            const int j = j0 + k % nj;
            const float px = (float)i * VOX - cx;
            const float py = (float)j * VOX - cy;
            const float rx = fmaf(py, s,  px * c);      //  px*c + py*s
            const float ry = fmaf(py, c, -px * s);      // -px*s + py*c
            if (fabsf(rx) < hx && fabsf(ry) < hy) {
                const int cell = i * HH + j;
                const int seg  = cell >> 5;
                const unsigned int bit = 1u << (cell & 31);
                const unsigned int old = atomicOr(&segmask[seg], bit);
                if (old == 0u) {                        // first claim
                    append = true;
                    ent = ((unsigned)b << 11) | (unsigned)seg;
                }
            }
        }
        const unsigned int bal = __ballot_sync(0xFFFFFFFFu, append);
        if (bal) {
            unsigned int base = 0u;
            if (lane == 0) base = atomicAdd(&g_wcount, (unsigned)__popc(bal));
            base = __shfl_sync(0xFFFFFFFFu, base, 0);
            if (append)
                g_wlist[base + __popc(bal & ((1u << lane) - 1u))] = ent;
        }
    }
}

// ---------------------------------------------------------------------------
// K2: consume worklist. One 32-cell segment per warp iteration.
// Lane l: channel-group g = l>>3, uint4 q = l&7. Each load instruction covers
// 4 channel planes (4 x 128B lines, fully coalesced); 16 instructions total
// in 4 opaque asm blocks -> <=4 latency waves per entry.
// ---------------------------------------------------------------------------
__global__ void __launch_bounds__(C_THREADS)
k_consume(const float* __restrict__ added,
          const float* __restrict__ orig,
          float* __restrict__ out) {
    const int lane = threadIdx.x & 31;
    const int wid  = threadIdx.x >> 5;
    const int gw   = blockIdx.x * (C_THREADS / 32) + wid;   // global warp id
    const int g    = lane >> 3;          // channel-group 0..3
    const int q    = lane & 7;           // uint4 index within segment

    __shared__ unsigned int s_i[BB], s_u[BB];
    if (threadIdx.x < BB) { s_i[threadIdx.x] = 0u; s_u[threadIdx.x] = 0u; }
    __syncthreads();

    const unsigned int nw = g_wcount;
    const unsigned int* au = (const unsigned int*)added;
    const unsigned int* ou = (const unsigned int*)orig;

    for (unsigned int e = gw; e < nw; e += NWARPS) {
        const unsigned int ent = g_wlist[e];
        const int seg = ent & (SEGS - 1);
        const int b   = ent >> 11;
        const int col = seg * 32 + q * 4;             // first cell of lane's uint4

        // per-lane base pointers at channel g (added) / 1+g (orig)
        const unsigned int* ap = au + ((size_t)b * CC + g)           * CELLS + col;
        const unsigned int* op = ou + ((size_t)b * (CC+1) + 1 + g)   * CELLS + col;

        uint4 va[4], vb[4], vc[4], vd[4];
        LDGB16(va, ap);                               // added ch g+{0,4,8,12}
        LDGB16(vb, ap + (size_t)16 * CELLS);          // added ch g+{16,...,28}
        LDGB16(vc, op);                               // orig  ch 1+g+{0..12}
        LDGB16(vd, op + (size_t)16 * CELLS);          // orig  ch 1+g+{16..28}

        uint4 pa, po;
        pa.x = va[0].x|va[1].x|va[2].x|va[3].x | vb[0].x|vb[1].x|vb[2].x|vb[3].x;
        pa.y = va[0].y|va[1].y|va[2].y|va[3].y | vb[0].y|vb[1].y|vb[2].y|vb[3].y;
        pa.z = va[0].z|va[1].z|va[2].z|va[3].z | vb[0].z|vb[1].z|vb[2].z|vb[3].z;
        pa.w = va[0].w|va[1].w|va[2].w|va[3].w | vb[0].w|vb[1].w|vb[2].w|vb[3].w;
        po.x = vc[0].x|vc[1].x|vc[2].x|vc[3].x | vd[0].x|vd[1].x|vd[2].x|vd[3].x;
        po.y = vc[0].y|vc[1].y|vc[2].y|vc[3].y | vd[0].y|vd[1].y|vd[2].y|vd[3].y;
        po.z = vc[0].z|vc[1].z|vc[2].z|vc[3].z | vd[0].z|vd[1].z|vd[2].z|vd[3].z;
        po.w = vc[0].w|vc[1].w|vc[2].w|vc[3].w | vd[0].w|vd[1].w|vd[2].w|vd[3].w;

        // combine the 4 channel-groups (lanes differing in bits 3,4)
        pa.x |= __shfl_xor_sync(0xFFFFFFFFu, pa.x, 8);
        pa.y |= __shfl_xor_sync(0xFFFFFFFFu, pa.y, 8);
        pa.z |= __shfl_xor_sync(0xFFFFFFFFu, pa.z, 8);
        pa.w |= __shfl_xor_sync(0xFFFFFFFFu, pa.w, 8);
        po.x |= __shfl_xor_sync(0xFFFFFFFFu, po.x, 8);
        po.y |= __shfl_xor_sync(0xFFFFFFFFu, po.y, 8);
        po.z |= __shfl_xor_sync(0xFFFFFFFFu, po.z, 8);
        po.w |= __shfl_xor_sync(0xFFFFFFFFu, po.w, 8);
        pa.x |= __shfl_xor_sync(0xFFFFFFFFu, pa.x, 16);
        pa.y |= __shfl_xor_sync(0xFFFFFFFFu, pa.y, 16);
        pa.z |= __shfl_xor_sync(0xFFFFFFFFu, pa.z, 16);
        pa.w |= __shfl_xor_sync(0xFFFFFFFFu, pa.w, 16);
        po.x |= __shfl_xor_sync(0xFFFFFFFFu, po.x, 16);
        po.y |= __shfl_xor_sync(0xFFFFFFFFu, po.y, 16);
        po.z |= __shfl_xor_sync(0xFFFFFFFFu, po.z, 16);
        po.w |= __shfl_xor_sync(0xFFFFFFFFu, po.w, 16);

        const unsigned int mw = g_segmask[b * SEGS + seg];
        if (lane == 0) g_segmask[b * SEGS + seg] = 0u;   // self-clean

        // each lane scores its 4 cells; all 4 groups duplicate -> /4 at the end
        const unsigned int paa[4] = {pa.x, pa.y, pa.z, pa.w};
        const unsigned int poa[4] = {po.x, po.y, po.z, po.w};
        unsigned int inter = 0u, uni = 0u;
        #pragma unroll
        for (int k = 0; k < 4; k++) {
            const bool m = (mw >> (q * 4 + k)) & 1u;
            const bool p = m && (paa[k] != 0u);       // sum!=0 <=> any bit (nonneg)
            const bool o = m && (poa[k] != 0u);
            inter += (unsigned)(p && o);
            uni   += (unsigned)(p || o);
        }
        const unsigned int vi = __reduce_add_sync(0xFFFFFFFFu, inter) >> 2;
        const unsigned int vu = __reduce_add_sync(0xFFFFFFFFu, uni)   >> 2;
        if (lane == 0) {
            if (vi) atomicAdd(&s_i[b], vi);
            if (vu) atomicAdd(&s_u[b], vu);
        }
    }
    __syncthreads();

    // flush block accumulators to global
    if (threadIdx.x < BB) {
        const unsigned int vi = s_i[threadIdx.x];
        const unsigned int vu = s_u[threadIdx.x];
        if (vi) atomicAdd(&g_inter[threadIdx.x], vi);
        if (vu) atomicAdd(&g_union[threadIdx.x], vu);
    }

    // ---- last-block finalization (+ scratch reset for next replay) --------
    __shared__ unsigned int s_last;
    if (threadIdx.x == 0) {
        __threadfence();
        s_last = (atomicAdd(&g_ticket, 1u) == (unsigned)(C_BLOCKS - 1)) ? 1u : 0u;
    }
    __syncthreads();
    if (s_last && wid == 0) {
        float iou = 0.0f;
        if (lane < BB) {
            const unsigned int ai  = g_inter[lane];
            const unsigned int au2 = g_union[lane];
            g_inter[lane] = 0u;                      // reset for next replay
            g_union[lane] = 0u;
            iou = (float)ai / fmaxf((float)au2, 1.0f);
        }
        #pragma unroll
        for (int off = 16; off > 0; off >>= 1)
            iou += __shfl_xor_sync(0xFFFFFFFFu, iou, off);
        if (lane == 0) {
            out[0] = (float)TT * iou / (float)BB;
            g_wcount = 0u;                           // reset worklist count
            __threadfence();
            g_ticket = 0u;                           // reset ticket
        }
    }
}

// ---------------------------------------------------------------------------
extern "C" void kernel_launch(void* const* d_in, const int* in_sizes, int n_in,
                              void* d_out, int out_size) {
    const float* added = (const float*)d_in[0];   // (16,32,256,256)
    const float* orig  = (const float*)d_in[1];   // (16,33,256,256)
    const float* boxes = (const float*)d_in[2];   // (16,20,7)
    (void)in_sizes; (void)n_in; (void)out_size;   // tf_ego unused

    k_rasterize<<<BB * TT, 128>>>(boxes);
    k_consume<<<C_BLOCKS, C_THREADS>>>(added, orig, (float*)d_out);
}

// round 14
// speedup vs baseline: 1.4250x; 1.2033x over previous
#include <cuda_runtime.h>
#include <cuda_bf16.h>
#include <cstdint>

// Problem constants (shapes fixed by dataset)
#define BB   16      // batch
#define CC   32      // channels in added; original has CC+1
#define HH   256     // grid H = W
#define TT   20      // boxes per batch
#define CELLS (HH*HH)
#define SEGS   (CELLS/32)    // 32-cell words (claim bitmap) = 2048/batch
#define CHUNKS (CELLS/8)     // 8-cell sector chunks = 8192/batch
#define VOX  0.8f
#define INVVOX 1.25f

#define C_BLOCKS 1024
#define C_THREADS 256
#define NWARPS  (C_BLOCKS * (C_THREADS/32))   // 8192 warps

// ALL 16 loads (8 added planes + 8 orig planes) in ONE opaque asm block:
// 16 outputs forced live together -> one latency wave per entry.
// Plane stride = CELLS*4B = 256KB; each load steps 4 planes = 1 MiB.
#define LDG16S(v, p1, p2)                                                     \
    asm volatile(                                                             \
        "ld.global.nc.u32 %0,  [%16];\n\t"                                    \
        "ld.global.nc.u32 %1,  [%16+1048576];\n\t"                            \
        "ld.global.nc.u32 %2,  [%16+2097152];\n\t"                            \
        "ld.global.nc.u32 %3,  [%16+3145728];\n\t"                            \
        "ld.global.nc.u32 %4,  [%16+4194304];\n\t"                            \
        "ld.global.nc.u32 %5,  [%16+5242880];\n\t"                            \
        "ld.global.nc.u32 %6,  [%16+6291456];\n\t"                            \
        "ld.global.nc.u32 %7,  [%16+7340032];\n\t"                            \
        "ld.global.nc.u32 %8,  [%17];\n\t"                                    \
        "ld.global.nc.u32 %9,  [%17+1048576];\n\t"                            \
        "ld.global.nc.u32 %10, [%17+2097152];\n\t"                            \
        "ld.global.nc.u32 %11, [%17+3145728];\n\t"                            \
        "ld.global.nc.u32 %12, [%17+4194304];\n\t"                            \
        "ld.global.nc.u32 %13, [%17+5242880];\n\t"                            \
        "ld.global.nc.u32 %14, [%17+6291456];\n\t"                            \
        "ld.global.nc.u32 %15, [%17+7340032];\n\t"                            \
        : "=r"((v)[0]),  "=r"((v)[1]),  "=r"((v)[2]),  "=r"((v)[3]),          \
          "=r"((v)[4]),  "=r"((v)[5]),  "=r"((v)[6]),  "=r"((v)[7]),          \
          "=r"((v)[8]),  "=r"((v)[9]),  "=r"((v)[10]), "=r"((v)[11]),         \
          "=r"((v)[12]), "=r"((v)[13]), "=r"((v)[14]), "=r"((v)[15])          \
        : "l"(p1), "l"(p2))

// Persistent scratch (no cudaMalloc). Static zero-init; consumers reset what
// they read so graph replays start clean.
__device__ unsigned int g_segmask[BB * SEGS];    // bit per cell (claim bitmap)
__device__ unsigned int g_wlist[BB * CHUNKS];    // packed (b<<13)|chunk
__device__ unsigned int g_wcount;
__device__ unsigned int g_inter[BB];
__device__ unsigned int g_union[BB];
__device__ unsigned int g_ticket;

// ---------------------------------------------------------------------------
// K1: rasterize boxes; claim cells via atomicOr on 32-cell words; the thread
// whose OR first touches an 8-cell chunk appends that chunk (warp-aggregated).
// ---------------------------------------------------------------------------
__global__ void __launch_bounds__(128)
k_rasterize(const float* __restrict__ boxes) {
    const int bt = blockIdx.x;            // 0 .. B*T-1
    const int b  = bt / TT;
    const float* bx = boxes + (size_t)bt * 7;

    const float cx = bx[0], cy = bx[1], cz = bx[2];
    const float dx = bx[3], dy = bx[4], dz = bx[5], yaw = bx[6];

    // z test constant per box: |0.8 - cz| <= dz/2 (reference uses <=)
    if (fabsf(VOX - cz) > 0.5f * dz) return;

    const float c  = cosf(yaw), s = sinf(yaw);
    const float hx = 0.5f * dx, hy = 0.5f * dy;

    // rotated-box AABB (meters), +1 cell safety margin
    const float ax = hx * fabsf(c) + hy * fabsf(s);
    const float ay = hx * fabsf(s) + hy * fabsf(c);
    const int i0 = max(0,      (int)floorf((cx - ax) * INVVOX) - 1);
    const int i1 = min(HH - 1, (int)ceilf ((cx + ax) * INVVOX) + 1);
    const int j0 = max(0,      (int)floorf((cy - ay) * INVVOX) - 1);
    const int j1 = min(HH - 1, (int)ceilf ((cy + ay) * INVVOX) + 1);
    const int ni = i1 - i0 + 1, nj = j1 - j0 + 1;
    const int n  = ni * nj;

    const int lane = threadIdx.x & 31;
    unsigned int* segmask = g_segmask + (size_t)b * SEGS;

    // warp-uniform trip count so ballots are safe
    for (int k = threadIdx.x; (k - lane) < n; k += blockDim.x) {
        bool append = false;
        unsigned int ent = 0u;
        if (k < n) {
            const int i = i0 + k / nj;
            const int j = j0 + k % nj;
            const float px = (float)i * VOX - cx;
            const float py = (float)j * VOX - cy;
            const float rx = fmaf(py, s,  px * c);      //  px*c + py*s
            const float ry = fmaf(py, c, -px * s);      // -px*s + py*c
            if (fabsf(rx) < hx && fabsf(ry) < hy) {
                const int cell  = i * HH + j;
                const int seg   = cell >> 5;
                const int chunk = cell >> 3;             // 8-cell chunk
                const unsigned int bit  = 1u << (cell & 31);
                const unsigned int bsh  = (unsigned)((chunk & 3) * 8);
                const unsigned int old  = atomicOr(&segmask[seg], bit);
                if (((old >> bsh) & 0xFFu) == 0u) {      // first claim of chunk
                    append = true;
                    ent = ((unsigned)b << 13) | (unsigned)chunk;
                }
            }
        }
        const unsigned int bal = __ballot_sync(0xFFFFFFFFu, append);
        if (bal) {
            unsigned int base = 0u;
            if (lane == 0) base = atomicAdd(&g_wcount, (unsigned)__popc(bal));
            base = __shfl_sync(0xFFFFFFFFu, base, 0);
            if (append)
                g_wlist[base + __popc(bal & ((1u << lane) - 1u))] = ent;
        }
    }
}

// ---------------------------------------------------------------------------
// K2: consume worklist. One 8-cell chunk (32B sector) per warp iteration.
// Lane l: cell = l&7, channel-group = l>>3. One asm block = all 64 channel
// planes as 16 sector-coalesced loads -> one latency wave, 2KB traffic/entry.
// ---------------------------------------------------------------------------
__global__ void __launch_bounds__(C_THREADS)
k_consume(const float* __restrict__ added,
          const float* __restrict__ orig,
          float* __restrict__ out) {
    const int lane = threadIdx.x & 31;
    const int wid  = threadIdx.x >> 5;
    const int gw   = blockIdx.x * (C_THREADS / 32) + wid;   // global warp id
    const int c    = lane & 7;           // cell within chunk
    const int cb   = lane >> 3;          // channel-group 0..3

    __shared__ unsigned int s_i[BB], s_u[BB];
    if (threadIdx.x < BB) { s_i[threadIdx.x] = 0u; s_u[threadIdx.x] = 0u; }
    __syncthreads();

    const unsigned int nw = g_wcount;
    const unsigned int* au = (const unsigned int*)added;
    const unsigned int* ou = (const unsigned int*)orig;

    for (unsigned int e = gw; e < nw; e += NWARPS) {
        const unsigned int ent = g_wlist[e];
        const int chunk = ent & (CHUNKS - 1);
        const int b     = ent >> 13;
        const int cell0 = chunk * 8;

        // lane pointers: added ch cb+4k (k=0..7), orig ch 1+cb+4k
        const unsigned int* ap = au + ((size_t)b * CC + cb)         * CELLS + cell0 + c;
        const unsigned int* op = ou + ((size_t)b * (CC+1) + 1 + cb) * CELLS + cell0 + c;

        unsigned int v[16];
        LDG16S(v, ap, op);

        unsigned int pa = v[0] | v[1] | v[2] | v[3] | v[4] | v[5] | v[6] | v[7];
        unsigned int po = v[8] | v[9] | v[10] | v[11] | v[12] | v[13] | v[14] | v[15];

        // combine the 4 channel-groups (lanes differing in bits 3,4)
        pa |= __shfl_xor_sync(0xFFFFFFFFu, pa, 8);
        po |= __shfl_xor_sync(0xFFFFFFFFu, po, 8);
        pa |= __shfl_xor_sync(0xFFFFFFFFu, pa, 16);
        po |= __shfl_xor_sync(0xFFFFFFFFu, po, 16);

        // mask byte for this chunk; clean own byte for next replay
        const int widx = b * SEGS + (chunk >> 2);
        const unsigned int bsh = (unsigned)((chunk & 3) * 8);
        const unsigned int mbyte = (g_segmask[widx] >> bsh) & 0xFFu;
        if (lane == 0)
            atomicAnd(&g_segmask[widx], ~(0xFFu << bsh));

        const bool m = (mbyte >> c) & 1u;
        const bool p = m && (pa != 0u);              // sum!=0 <=> any bit (nonneg)
        const bool o = m && (po != 0u);
        // each cell counted once per channel-group (x4) -> divide at the end
        const unsigned int vi = __reduce_add_sync(0xFFFFFFFFu, (unsigned)(p && o)) >> 2;
        const unsigned int vu = __reduce_add_sync(0xFFFFFFFFu, (unsigned)(p || o)) >> 2;
        if (lane == 0) {
            if (vi) atomicAdd(&s_i[b], vi);
            if (vu) atomicAdd(&s_u[b], vu);
        }
    }
    __syncthreads();

    // flush block accumulators to global
    if (threadIdx.x < BB) {
        const unsigned int vi = s_i[threadIdx.x];
        const unsigned int vu = s_u[threadIdx.x];
        if (vi) atomicAdd(&g_inter[threadIdx.x], vi);
        if (vu) atomicAdd(&g_union[threadIdx.x], vu);
    }

    // ---- last-block finalization (+ scratch reset for next replay) --------
    __shared__ unsigned int s_last;
    if (threadIdx.x == 0) {
        __threadfence();
        s_last = (atomicAdd(&g_ticket, 1u) == (unsigned)(C_BLOCKS - 1)) ? 1u : 0u;
    }
    __syncthreads();
    if (s_last && wid == 0) {
        float iou = 0.0f;
        if (lane < BB) {
            const unsigned int ai  = g_inter[lane];
            const unsigned int au2 = g_union[lane];
            g_inter[lane] = 0u;                      // reset for next replay
            g_union[lane] = 0u;
            iou = (float)ai / fmaxf((float)au2, 1.0f);
        }
        #pragma unroll
        for (int off = 16; off > 0; off >>= 1)
            iou += __shfl_xor_sync(0xFFFFFFFFu, iou, off);
        if (lane == 0) {
            out[0] = (float)TT * iou / (float)BB;
            g_wcount = 0u;                           // reset worklist count
            __threadfence();
            g_ticket = 0u;                           // reset ticket
        }
    }
}

// ---------------------------------------------------------------------------
extern "C" void kernel_launch(void* const* d_in, const int* in_sizes, int n_in,
                              void* d_out, int out_size) {
    const float* added = (const float*)d_in[0];   // (16,32,256,256)
    const float* orig  = (const float*)d_in[1];   // (16,33,256,256)
    const float* boxes = (const float*)d_in[2];   // (16,20,7)
    (void)in_sizes; (void)n_in; (void)out_size;   // tf_ego unused

    k_rasterize<<<BB * TT, 128>>>(boxes);
    k_consume<<<C_BLOCKS, C_THREADS>>>(added, orig, (float*)d_out);
}

// round 15
// speedup vs baseline: 1.5863x; 1.1132x over previous
#include <cuda_runtime.h>
#include <cuda_bf16.h>
#include <cstdint>

// Problem constants (shapes fixed by dataset)
#define BB   16      // batch
#define CC   32      // channels in added; original has CC+1
#define HH   256     // grid H = W
#define TT   20      // boxes per batch
#define CELLS (HH*HH)
#define SEGS    (CELLS/32)   // 32-cell claim words = 2048/batch
#define CHUNK16 (CELLS/16)   // 16-cell (64B) chunks = 4096/batch
#define VOX  0.8f
#define INVVOX 1.25f

#define NB    512            // persistent blocks (all co-resident: see launch_bounds)
#define NT    256
#define NWARPS (NB * (NT/32))   // 4096 warps

// 16 loads in ONE opaque asm block (16 outputs live together -> one wave).
// Plane stride = 2 channels = 512KB (lane's channel-group interleave).
#define LDG16P(v, p)                                                          \
    asm volatile(                                                             \
        "ld.global.nc.u32 %0,  [%16];\n\t"                                    \
        "ld.global.nc.u32 %1,  [%16+524288];\n\t"                             \
        "ld.global.nc.u32 %2,  [%16+1048576];\n\t"                            \
        "ld.global.nc.u32 %3,  [%16+1572864];\n\t"                            \
        "ld.global.nc.u32 %4,  [%16+2097152];\n\t"                            \
        "ld.global.nc.u32 %5,  [%16+2621440];\n\t"                            \
        "ld.global.nc.u32 %6,  [%16+3145728];\n\t"                            \
        "ld.global.nc.u32 %7,  [%16+3670016];\n\t"                            \
        "ld.global.nc.u32 %8,  [%16+4194304];\n\t"                            \
        "ld.global.nc.u32 %9,  [%16+4718592];\n\t"                            \
        "ld.global.nc.u32 %10, [%16+5242880];\n\t"                            \
        "ld.global.nc.u32 %11, [%16+5767168];\n\t"                            \
        "ld.global.nc.u32 %12, [%16+6291456];\n\t"                            \
        "ld.global.nc.u32 %13, [%16+6815744];\n\t"                            \
        "ld.global.nc.u32 %14, [%16+7340032];\n\t"                            \
        "ld.global.nc.u32 %15, [%16+7864320];\n\t"                            \
        : "=r"((v)[0]),  "=r"((v)[1]),  "=r"((v)[2]),  "=r"((v)[3]),          \
          "=r"((v)[4]),  "=r"((v)[5]),  "=r"((v)[6]),  "=r"((v)[7]),          \
          "=r"((v)[8]),  "=r"((v)[9]),  "=r"((v)[10]), "=r"((v)[11]),         \
          "=r"((v)[12]), "=r"((v)[13]), "=r"((v)[14]), "=r"((v)[15])          \
        : "l"(p))

// Persistent scratch (no cudaMalloc). Static zero-init; the finalizer resets
// everything so every graph replay starts clean.
__device__ unsigned int g_segmask[BB * SEGS];     // bit per cell (claim bitmap)
__device__ unsigned int g_wlist[BB * CHUNK16];    // packed (b<<12)|chunk16
__device__ unsigned int g_wcount;
__device__ unsigned int g_arrive;                 // phase-1 barrier
__device__ unsigned int g_inter[BB];
__device__ unsigned int g_union[BB];
__device__ unsigned int g_ticket;

__global__ void __launch_bounds__(NT, 4)          // <=64 regs: 4 blocks/SM
k_fused(const float* __restrict__ added,
        const float* __restrict__ orig,
        const float* __restrict__ boxes,
        float* __restrict__ out) {
    const int tid  = threadIdx.x;
    const int lane = tid & 31;
    const int wid  = tid >> 5;

    // ===================== PHASE 1: rasterize (blocks 0..319) ==============
    if (blockIdx.x < BB * TT) {
        const int bt = blockIdx.x;
        const int b  = bt / TT;
        const float* bx = boxes + (size_t)bt * 7;
        const float cx = bx[0], cy = bx[1], cz = bx[2];
        const float dx = bx[3], dy = bx[4], dz = bx[5], yaw = bx[6];

        // z test constant per box: |0.8 - cz| <= dz/2 (reference uses <=)
        if (fabsf(VOX - cz) <= 0.5f * dz) {
            const float c  = cosf(yaw), s = sinf(yaw);
            const float hx = 0.5f * dx, hy = 0.5f * dy;
            const float ax = hx * fabsf(c) + hy * fabsf(s);   // rotated AABB
            const float ay = hx * fabsf(s) + hy * fabsf(c);
            const int i0 = max(0,      (int)floorf((cx - ax) * INVVOX) - 1);
            const int i1 = min(HH - 1, (int)ceilf ((cx + ax) * INVVOX) + 1);
            const int j0 = max(0,      (int)floorf((cy - ay) * INVVOX) - 1);
            const int j1 = min(HH - 1, (int)ceilf ((cy + ay) * INVVOX) + 1);
            const int ni = i1 - i0 + 1, nj = j1 - j0 + 1;
            const int n  = ni * nj;

            unsigned int* segmask = g_segmask + (size_t)b * SEGS;

            // warp-uniform trip count so ballots are safe
            for (int k = tid; (k - lane) < n; k += NT) {
                bool append = false;
                unsigned int ent = 0u;
                if (k < n) {
                    const int i = i0 + k / nj;
                    const int j = j0 + k % nj;
                    const float px = (float)i * VOX - cx;
                    const float py = (float)j * VOX - cy;
                    const float rx = fmaf(py, s,  px * c);   //  px*c + py*s
                    const float ry = fmaf(py, c, -px * s);   // -px*s + py*c
                    if (fabsf(rx) < hx && fabsf(ry) < hy) {
                        const int cell = i * HH + j;
                        const int seg  = cell >> 5;
                        const int ch16 = cell >> 4;          // 16-cell chunk
                        const unsigned int bit = 1u << (cell & 31);
                        const unsigned int hsh = (unsigned)((ch16 & 1) * 16);
                        const unsigned int old = atomicOr(&segmask[seg], bit);
                        if (((old >> hsh) & 0xFFFFu) == 0u) { // first claim
                            append = true;
                            ent = ((unsigned)b << 12) | (unsigned)ch16;
                        }
                    }
                }
                const unsigned int bal = __ballot_sync(0xFFFFFFFFu, append);
                if (bal) {
                    unsigned int base = 0u;
                    if (lane == 0)
                        base = atomicAdd(&g_wcount, (unsigned)__popc(bal));
                    base = __shfl_sync(0xFFFFFFFFu, base, 0);
                    if (append)
                        g_wlist[base + __popc(bal & ((1u << lane) - 1u))] = ent;
                }
            }
        }
    }

    // ===================== global barrier (all blocks resident) ============
    __syncthreads();
    if (tid == 0) {
        __threadfence();
        atomicAdd(&g_arrive, 1u);
        while (*((volatile unsigned int*)&g_arrive) < (unsigned)NB)
            __nanosleep(64);
    }
    __syncthreads();
    __threadfence();

    // ===================== PHASE 2: consume worklist =======================
    __shared__ unsigned int s_i[BB], s_u[BB];
    if (tid < BB) { s_i[tid] = 0u; s_u[tid] = 0u; }
    __syncthreads();

    const unsigned int nw = *((volatile unsigned int*)&g_wcount);
    const unsigned int* au = (const unsigned int*)added;
    const unsigned int* ou = (const unsigned int*)orig;
    const int c  = lane & 15;            // cell within 16-cell chunk
    const int cb = lane >> 4;            // channel parity 0/1
    const int gw = blockIdx.x * (NT / 32) + wid;

    for (unsigned int e = gw; e < nw; e += NWARPS) {
        const unsigned int ent = g_wlist[e];
        const int ch16  = ent & (CHUNK16 - 1);
        const int b     = ent >> 12;
        const int cell0 = ch16 * 16;

        // lane loads channels cb, cb+2, ..., cb+30 (added) / 1+cb.. (orig)
        const unsigned int* ap = au + ((size_t)b * CC + cb)         * CELLS + cell0 + c;
        const unsigned int* op = ou + ((size_t)b * (CC+1) + 1 + cb) * CELLS + cell0 + c;

        unsigned int v[16];
        LDG16P(v, ap);                   // wave 1: 16 added planes
        unsigned int pa = v[0]|v[1]|v[2]|v[3]|v[4]|v[5]|v[6]|v[7]
                        | v[8]|v[9]|v[10]|v[11]|v[12]|v[13]|v[14]|v[15];
        LDG16P(v, op);                   // wave 2: 16 orig planes
        unsigned int po = v[0]|v[1]|v[2]|v[3]|v[4]|v[5]|v[6]|v[7]
                        | v[8]|v[9]|v[10]|v[11]|v[12]|v[13]|v[14]|v[15];

        // combine the 2 channel parities (lanes differing in bit 4)
        pa |= __shfl_xor_sync(0xFFFFFFFFu, pa, 16);
        po |= __shfl_xor_sync(0xFFFFFFFFu, po, 16);

        // mask halfword for this chunk; clean it for the next replay
        const int widx = b * SEGS + (ch16 >> 1);
        const unsigned int hsh = (unsigned)((ch16 & 1) * 16);
        const unsigned int mh = (g_segmask[widx] >> hsh) & 0xFFFFu;
        if (lane == 0)
            atomicAnd(&g_segmask[widx], ~(0xFFFFu << hsh));

        const bool m = (mh >> c) & 1u;
        const bool p = m && (pa != 0u);  // sum!=0 <=> any bit set (nonneg data)
        const bool o = m && (po != 0u);
        // cells duplicated across the 2 parities -> halve the counts
        const unsigned int vi = __reduce_add_sync(0xFFFFFFFFu, (unsigned)(p && o)) >> 1;
        const unsigned int vu = __reduce_add_sync(0xFFFFFFFFu, (unsigned)(p || o)) >> 1;
        if (lane == 0) {
            if (vi) atomicAdd(&s_i[b], vi);
            if (vu) atomicAdd(&s_u[b], vu);
        }
    }
    __syncthreads();

    if (tid < BB) {
        const unsigned int vi = s_i[tid];
        const unsigned int vu = s_u[tid];
        if (vi) atomicAdd(&g_inter[tid], vi);
        if (vu) atomicAdd(&g_union[tid], vu);
    }

    // ===================== finalize (+ scratch reset for next replay) ======
    __shared__ unsigned int s_last;
    if (tid == 0) {
        __threadfence();
        s_last = (atomicAdd(&g_ticket, 1u) == (unsigned)(NB - 1)) ? 1u : 0u;
    }
    __syncthreads();
    if (s_last && wid == 0) {
        float iou = 0.0f;
        if (lane < BB) {
            const unsigned int ai  = g_inter[lane];
            const unsigned int au2 = g_union[lane];
            g_inter[lane] = 0u;
            g_union[lane] = 0u;
            iou = (float)ai / fmaxf((float)au2, 1.0f);
        }
        #pragma unroll
        for (int off = 16; off > 0; off >>= 1)
            iou += __shfl_xor_sync(0xFFFFFFFFu, iou, off);
        if (lane == 0) {
            out[0] = (float)TT * iou / (float)BB;
            g_wcount = 0u;
            g_arrive = 0u;
            __threadfence();
            g_ticket = 0u;
        }
    }
}

// ---------------------------------------------------------------------------
extern "C" void kernel_launch(void* const* d_in, const int* in_sizes, int n_in,
                              void* d_out, int out_size) {
    const float* added = (const float*)d_in[0];   // (16,32,256,256)
    const float* orig  = (const float*)d_in[1];   // (16,33,256,256)
    const float* boxes = (const float*)d_in[2];   // (16,20,7)
    (void)in_sizes; (void)n_in; (void)out_size;   // tf_ego unused

    k_fused<<<NB, NT>>>(added, orig, boxes, (float*)d_out);
}

// round 17
// speedup vs baseline: 1.8114x; 1.1419x over previous
#include <cuda_runtime.h>
#include <cuda_bf16.h>
#include <cstdint>

// Problem constants (shapes fixed by dataset)
#define BB   16      // batch
#define CC   32      // channels in added; original has CC+1
#define HH   256     // grid H = W
#define TT   20      // boxes per batch
#define CELLS (HH*HH)
#define CHUNK16 (CELLS/16)   // 16-cell (64B) chunks = 4096/batch
#define VOX  0.8f
#define INVVOX 1.25f

#define NB    444            // 3 blocks/SM x 148 SMs -> all co-resident
#define NT    256
#define NWARPS (NB * (NT/32))   // 3552 warps

// ALL 32 channel-plane loads (16 added + 16 orig) in ONE opaque asm block:
// 32 outputs forced live simultaneously -> exactly one latency wave per entry.
// Stride between loads = 2 channel planes = 512KB.
#define LDG32P(v, p1, p2)                                                     \
    asm volatile(                                                             \
        "ld.global.nc.u32 %0,  [%32];\n\t"                                    \
        "ld.global.nc.u32 %1,  [%32+524288];\n\t"                             \
        "ld.global.nc.u32 %2,  [%32+1048576];\n\t"                            \
        "ld.global.nc.u32 %3,  [%32+1572864];\n\t"                            \
        "ld.global.nc.u32 %4,  [%32+2097152];\n\t"                            \
        "ld.global.nc.u32 %5,  [%32+2621440];\n\t"                            \
        "ld.global.nc.u32 %6,  [%32+3145728];\n\t"                            \
        "ld.global.nc.u32 %7,  [%32+3670016];\n\t"                            \
        "ld.global.nc.u32 %8,  [%32+4194304];\n\t"                            \
        "ld.global.nc.u32 %9,  [%32+4718592];\n\t"                            \
        "ld.global.nc.u32 %10, [%32+5242880];\n\t"                            \
        "ld.global.nc.u32 %11, [%32+5767168];\n\t"                            \
        "ld.global.nc.u32 %12, [%32+6291456];\n\t"                            \
        "ld.global.nc.u32 %13, [%32+6815744];\n\t"                            \
        "ld.global.nc.u32 %14, [%32+7340032];\n\t"                            \
        "ld.global.nc.u32 %15, [%32+7864320];\n\t"                            \
        "ld.global.nc.u32 %16, [%33];\n\t"                                    \
        "ld.global.nc.u32 %17, [%33+524288];\n\t"                             \
        "ld.global.nc.u32 %18, [%33+1048576];\n\t"                            \
        "ld.global.nc.u32 %19, [%33+1572864];\n\t"                            \
        "ld.global.nc.u32 %20, [%33+2097152];\n\t"                            \
        "ld.global.nc.u32 %21, [%33+2621440];\n\t"                            \
        "ld.global.nc.u32 %22, [%33+3145728];\n\t"                            \
        "ld.global.nc.u32 %23, [%33+3670016];\n\t"                            \
        "ld.global.nc.u32 %24, [%33+4194304];\n\t"                            \
        "ld.global.nc.u32 %25, [%33+4718592];\n\t"                            \
        "ld.global.nc.u32 %26, [%33+5242880];\n\t"                            \
        "ld.global.nc.u32 %27, [%33+5767168];\n\t"                            \
        "ld.global.nc.u32 %28, [%33+6291456];\n\t"                            \
        "ld.global.nc.u32 %29, [%33+6815744];\n\t"                            \
        "ld.global.nc.u32 %30, [%33+7340032];\n\t"                            \
        "ld.global.nc.u32 %31, [%33+7864320];\n\t"                            \
        : "=r"((v)[0]),  "=r"((v)[1]),  "=r"((v)[2]),  "=r"((v)[3]),          \
          "=r"((v)[4]),  "=r"((v)[5]),  "=r"((v)[6]),  "=r"((v)[7]),          \
          "=r"((v)[8]),  "=r"((v)[9]),  "=r"((v)[10]), "=r"((v)[11]),         \
          "=r"((v)[12]), "=r"((v)[13]), "=r"((v)[14]), "=r"((v)[15]),         \
          "=r"((v)[16]), "=r"((v)[17]), "=r"((v)[18]), "=r"((v)[19]),         \
          "=r"((v)[20]), "=r"((v)[21]), "=r"((v)[22]), "=r"((v)[23]),         \
          "=r"((v)[24]), "=r"((v)[25]), "=r"((v)[26]), "=r"((v)[27]),         \
          "=r"((v)[28]), "=r"((v)[29]), "=r"((v)[30]), "=r"((v)[31])          \
        : "l"(p1), "l"(p2))

// Persistent scratch (no cudaMalloc). Static zero-init; the kernel resets
// everything so every graph replay starts clean.
__device__ unsigned int g_cmask[BB * CHUNK16];   // 16-bit claim mask per chunk
__device__ unsigned int g_wlist[BB * CHUNK16];   // packed b|chunk|mask16
__device__ unsigned int g_wcount;
__device__ unsigned int g_arrive;                // phase-1 barrier
__device__ unsigned int g_inter[BB];
__device__ unsigned int g_union[BB];
__device__ unsigned int g_ticket;

__global__ void __launch_bounds__(NT, 3)         // <=85 regs: 3 blocks/SM
k_fused(const float* __restrict__ added,
        const float* __restrict__ orig,
        const float* __restrict__ boxes,
        float* __restrict__ out) {
    const int tid  = threadIdx.x;
    const int lane = tid & 31;
    const int wid  = tid >> 5;

    // ============ PHASE 1: rasterize by (row, chunk) tasks =================
    // blocks 0..BB*TT-1: one block per box.
    if (blockIdx.x < BB * TT) {
        const int bt = blockIdx.x;
        const int b  = bt / TT;
        const float* bx = boxes + (size_t)bt * 7;
        const float cx = bx[0], cy = bx[1], cz = bx[2];
        const float dx = bx[3], dy = bx[4], dz = bx[5], yaw = bx[6];

        // z test constant per box: |0.8 - cz| <= dz/2 (reference uses <=)
        if (fabsf(VOX - cz) <= 0.5f * dz) {
            const float c  = cosf(yaw), s = sinf(yaw);
            const float hx = 0.5f * dx, hy = 0.5f * dy;
            const float ax = hx * fabsf(c) + hy * fabsf(s);   // rotated AABB
            const float ay = hx * fabsf(s) + hy * fabsf(c);
            const int i0 = max(0,      (int)floorf((cx - ax) * INVVOX) - 1);
            const int i1 = min(HH - 1, (int)ceilf ((cx + ax) * INVVOX) + 1);
            const int j0 = max(0,      (int)floorf((cy - ay) * INVVOX) - 1);
            const int j1 = min(HH - 1, (int)ceilf ((cy + ay) * INVVOX) + 1);
            const int ni  = i1 - i0 + 1;
            const int ch0 = j0 >> 4;
            const int nch = (j1 >> 4) - ch0 + 1;      // chunks per row (<=17)
            const int n   = ni * nch;                 // (row, chunk) tasks

            // warp-uniform trip count so ballots are safe
            for (int t = tid; (t - lane) < n; t += NT) {
                bool append = false;
                unsigned int ent = 0u;
                if (t < n) {
                    const int i   = i0 + t / nch;
                    const int chc = ch0 + t % nch;    // chunk column (j>>4)
                    const float px = (float)i * VOX - cx;
                    const float pxc =  px * c;
                    const float pxs = -px * s;
                    unsigned int m16 = 0u;
                    #pragma unroll
                    for (int k = 0; k < 16; k++) {
                        const int j = chc * 16 + k;
                        const float py = (float)j * VOX - cy;
                        const float rx = fmaf(py, s, pxc);   //  px*c + py*s
                        const float ry = fmaf(py, c, pxs);   // -px*s + py*c
                        if (fabsf(rx) < hx && fabsf(ry) < hy) m16 |= (1u << k);
                    }
                    if (m16 != 0u) {
                        const int ch16 = i * 16 + chc;       // chunk id in batch
                        const unsigned int old =
                            atomicOr(&g_cmask[b * CHUNK16 + ch16], m16);
                        const unsigned int neu = m16 & ~old; // newly claimed
                        if (neu != 0u) {
                            append = true;
                            ent = ((unsigned)b << 28) | ((unsigned)ch16 << 16) | neu;
                        }
                    }
                }
                const unsigned int bal = __ballot_sync(0xFFFFFFFFu, append);
                if (bal) {
                    unsigned int base = 0u;
                    if (lane == 0)
                        base = atomicAdd(&g_wcount, (unsigned)__popc(bal));
                    base = __shfl_sync(0xFFFFFFFFu, base, 0);
                    if (append)
                        g_wlist[base + __popc(bal & ((1u << lane) - 1u))] = ent;
                }
            }
        }
    }

    // ============ global barrier (all NB blocks resident) ==================
    __syncthreads();
    if (tid == 0) {
        __threadfence();
        atomicAdd(&g_arrive, 1u);
        while (*((volatile unsigned int*)&g_arrive) < (unsigned)NB)
            __nanosleep(64);
    }
    __syncthreads();
    __threadfence();

    // ============ bulk-zero claim masks for the next replay ================
    // (rasterize is done; nobody reads g_cmask after the barrier)
    {
        const int idx = blockIdx.x * NT + tid;
        if (idx < BB * CHUNK16) g_cmask[idx] = 0u;
    }

    // ============ PHASE 2: consume worklist ================================
    __shared__ unsigned int s_i[BB], s_u[BB];
    if (tid < BB) { s_i[tid] = 0u; s_u[tid] = 0u; }
    __syncthreads();

    const unsigned int nw = *((volatile unsigned int*)&g_wcount);
    const unsigned int* au = (const unsigned int*)added;
    const unsigned int* ou = (const unsigned int*)orig;
    const int c   = lane & 15;           // cell within 16-cell chunk
    const int par = lane >> 4;           // channel parity 0/1
    const int gw  = blockIdx.x * (NT / 32) + wid;

    for (unsigned int e = gw; e < nw; e += NWARPS) {
        const unsigned int ent = g_wlist[e];
        const int b     = (int)(ent >> 28);
        const int ch16  = (int)((ent >> 16) & 0xFFFu);
        const unsigned int m16 = ent & 0xFFFFu;
        const int cell0 = ch16 * 16;

        // lane loads channels par, par+2, ..., par+30 (added) / 1+par.. (orig)
        const unsigned int* ap = au + ((size_t)b * CC + par)         * CELLS + cell0 + c;
        const unsigned int* op = ou + ((size_t)b * (CC+1) + 1 + par) * CELLS + cell0 + c;

        unsigned int v[32];
        LDG32P(v, ap, op);               // single wave: all 64 channel planes

        unsigned int pa = v[0]|v[1]|v[2]|v[3]|v[4]|v[5]|v[6]|v[7]
                        | v[8]|v[9]|v[10]|v[11]|v[12]|v[13]|v[14]|v[15];
        unsigned int po = v[16]|v[17]|v[18]|v[19]|v[20]|v[21]|v[22]|v[23]
                        | v[24]|v[25]|v[26]|v[27]|v[28]|v[29]|v[30]|v[31];

        // combine the 2 channel parities (lanes differing in bit 4)
        pa |= __shfl_xor_sync(0xFFFFFFFFu, pa, 16);
        po |= __shfl_xor_sync(0xFFFFFFFFu, po, 16);

        const bool m = (m16 >> c) & 1u;
        const bool p = m && (pa != 0u);  // sum!=0 <=> any bit set (nonneg data)
        const bool o = m && (po != 0u);
        // cells duplicated across the 2 parities -> halve the counts
        const unsigned int vi = __reduce_add_sync(0xFFFFFFFFu, (unsigned)(p && o)) >> 1;
        const unsigned int vu = __reduce_add_sync(0xFFFFFFFFu, (unsigned)(p || o)) >> 1;
        if (lane == 0) {
            if (vi) atomicAdd(&s_i[b], vi);
            if (vu) atomicAdd(&s_u[b], vu);
        }
    }
    __syncthreads();

    if (tid < BB) {
        const unsigned int vi = s_i[tid];
        const unsigned int vu = s_u[tid];
        if (vi) atomicAdd(&g_inter[tid], vi);
        if (vu) atomicAdd(&g_union[tid], vu);
    }

    // ============ finalize (+ scratch reset for next replay) ===============
    __shared__ unsigned int s_last;
    if (tid == 0) {
        __threadfence();
        s_last = (atomicAdd(&g_ticket, 1u) == (unsigned)(NB - 1)) ? 1u : 0u;
    }
    __syncthreads();
    if (s_last && wid == 0) {
        float iou = 0.0f;
        if (lane < BB) {
            const unsigned int ai  = g_inter[lane];
            const unsigned int au2 = g_union[lane];
            g_inter[lane] = 0u;
            g_union[lane] = 0u;
            iou = (float)ai / fmaxf((float)au2, 1.0f);
        }
        #pragma unroll
        for (int off = 16; off > 0; off >>= 1)
            iou += __shfl_xor_sync(0xFFFFFFFFu, iou, off);
        if (lane == 0) {
            out[0] = (float)TT * iou / (float)BB;
            g_wcount = 0u;
            g_arrive = 0u;
            __threadfence();
            g_ticket = 0u;
        }
    }
}

// ---------------------------------------------------------------------------
extern "C" void kernel_launch(void* const* d_in, const int* in_sizes, int n_in,
                              void* d_out, int out_size) {
    const float* added = (const float*)d_in[0];   // (16,32,256,256)
    const float* orig  = (const float*)d_in[1];   // (16,33,256,256)
    const float* boxes = (const float*)d_in[2];   // (16,20,7)
    (void)in_sizes; (void)n_in; (void)out_size;   // tf_ego unused

    k_fused<<<NB, NT>>>(added, orig, boxes, (float*)d_out);
}